// round 3
// baseline (speedup 1.0000x reference)
#include <cuda_runtime.h>
#include <cuda_fp16.h>
#include <math.h>

typedef unsigned long long u64;

// Problem caps (from reference): N=50000 nodes, E=800000 edges, D=64.
#define MAXN 50000
#define MAXE 800000
#define SCAN_B 256
#define MAXBLK ((MAXN + SCAN_B - 1) / SCAN_B)   // 196

// Scratch (device globals — no allocation allowed in kernel_launch).
__device__ __align__(16) __half2 g_tmph[MAXN * 32];  // h @ W in fp16 (64 vals/row = 128B = 1 L2 line)
__device__ float g_h[MAXN * 64];      // layer activations (input to next layer)
__device__ float g_dinv[MAXN];        // 1/sqrt(deg+1)
__device__ int   g_deg[MAXN];
__device__ int   g_cursor[MAXN];
__device__ int   g_rowptr[MAXN + 1];
__device__ int   g_col[MAXE];         // CSR by dst: src indices
__device__ int   g_bsum[MAXBLK];
__device__ int   g_boff[MAXBLK];

// ---------------------------------------------------------------------------
// CSR build
// ---------------------------------------------------------------------------
__global__ void k_init(int n) {
    int i = blockIdx.x * blockDim.x + threadIdx.x;
    if (i < n) { g_deg[i] = 0; g_cursor[i] = 0; }
}

__global__ void k_count(const int* __restrict__ dst, int e) {
    int i = blockIdx.x * blockDim.x + threadIdx.x;
    if (i < e) atomicAdd(&g_deg[dst[i]], 1);
}

__global__ void k_scanA(int n) {
    int i = blockIdx.x * SCAN_B + threadIdx.x;
    int lane = threadIdx.x & 31, wid = threadIdx.x >> 5;
    int v = (i < n) ? g_deg[i] : 0;
    if (i < n) g_dinv[i] = rsqrtf((float)(v + 1));   // +1 self-loop

    int x = v;
#pragma unroll
    for (int o = 1; o < 32; o <<= 1) {
        int t = __shfl_up_sync(0xffffffffu, x, o);
        if (lane >= o) x += t;
    }
    __shared__ int wsum[8];
    if (lane == 31) wsum[wid] = x;
    __syncthreads();
    if (wid == 0) {
        int s = (lane < 8) ? wsum[lane] : 0;
#pragma unroll
        for (int o = 1; o < 8; o <<= 1) {
            int t = __shfl_up_sync(0xffffffffu, s, o);
            if (lane >= o) s += t;
        }
        if (lane < 8) wsum[lane] = s;
    }
    __syncthreads();
    int excl = x - v + (wid ? wsum[wid - 1] : 0);
    if (i < n) g_rowptr[i] = excl;
    if (threadIdx.x == SCAN_B - 1) g_bsum[blockIdx.x] = wsum[7];
}

__global__ void k_scanB(int nb, int n) {
    int tid = threadIdx.x;
    int lane = tid & 31, wid = tid >> 5;
    int v = (tid < nb) ? g_bsum[tid] : 0;
    int x = v;
#pragma unroll
    for (int o = 1; o < 32; o <<= 1) {
        int t = __shfl_up_sync(0xffffffffu, x, o);
        if (lane >= o) x += t;
    }
    __shared__ int wsum[8];
    if (lane == 31) wsum[wid] = x;
    __syncthreads();
    if (wid == 0) {
        int s = (lane < 8) ? wsum[lane] : 0;
#pragma unroll
        for (int o = 1; o < 8; o <<= 1) {
            int t = __shfl_up_sync(0xffffffffu, s, o);
            if (lane >= o) s += t;
        }
        if (lane < 8) wsum[lane] = s;
    }
    __syncthreads();
    int excl = x - v + (wid ? wsum[wid - 1] : 0);
    if (tid < nb) g_boff[tid] = excl;
    if (tid == SCAN_B - 1) g_rowptr[n] = wsum[7];
}

__global__ void k_scanC(int n) {
    int i = blockIdx.x * blockDim.x + threadIdx.x;
    if (i < n) g_rowptr[i] += g_boff[i >> 8];
}

__global__ void k_fill(const int* __restrict__ src, const int* __restrict__ dst, int e) {
    int i = blockIdx.x * blockDim.x + threadIdx.x;
    if (i < e) {
        int d = dst[i];
        int pos = g_rowptr[d] + atomicAdd(&g_cursor[d], 1);
        g_col[pos] = src[i];
    }
}

// ---------------------------------------------------------------------------
// GEMM: tmp[n,64] = A[n,64] @ W[64,64], fp32 math via packed f32x2 FFMA2,
// output stored as fp16. Accumulators hold (even-k, odd-k) partial sums.
// Block 256 threads, tile 128x64, micro-tile 8 rows x 4 cols per thread.
// ---------------------------------------------------------------------------
__device__ __forceinline__ void ffma2(u64 &d, u64 a, u64 b) {
    asm("fma.rn.f32x2 %0, %1, %2, %3;" : "=l"(d) : "l"(a), "l"(b), "l"(d));
}

__global__ void k_gemm(const float* __restrict__ Aext, int useExt,
                       const float* __restrict__ W, int n) {
    __shared__ float As[128][64];   // 32 KB row-major (k contiguous)
    __shared__ u64 Wp[32][64];      // 16 KB: Wp[kk][c] = (W[2kk][c], W[2kk+1][c])
    const float* A = useExt ? Aext : g_h;
    int tid = threadIdx.x;
    int block_row = blockIdx.x * 128;

    // Pack W into (even,odd) k-pairs per output column.
#pragma unroll
    for (int j = 0; j < 8; ++j) {
        int idx = tid + 256 * j;        // 2048 u64 total
        int kk = idx >> 6, c = idx & 63;
        float lo = W[(2 * kk) * 64 + c];
        float hi = W[(2 * kk + 1) * 64 + c];
        u64 p; asm("mov.b64 %0,{%1,%2};" : "=l"(p) : "f"(lo), "f"(hi));
        Wp[kk][c] = p;
    }
    // Load A tile (float4 coalesced).
#pragma unroll
    for (int j = 0; j < 8; ++j) {
        int idx = tid + 256 * j;
        int r = idx >> 4, k4 = idx & 15;
        int gr = block_row + r;
        float4 v = make_float4(0.f, 0.f, 0.f, 0.f);
        if (gr < n) v = ((const float4*)A)[gr * 16 + k4];
        ((float4*)&As[r][0])[k4] = v;
    }
    __syncthreads();

    int tr = tid >> 4;   // rows tr*8 .. tr*8+7
    int tc = tid & 15;   // cols tc*4 .. tc*4+3
    u64 acc[8][4];
#pragma unroll
    for (int j = 0; j < 8; ++j)
#pragma unroll
        for (int c = 0; c < 4; ++c) acc[j][c] = 0ULL;   // (0.f,0.f)

#pragma unroll 2
    for (int kq = 0; kq < 16; ++kq) {   // 4 k-values per iteration
        u64 b[2][4];
#pragma unroll
        for (int h = 0; h < 2; ++h) {
            ulonglong2 t0 = *(const ulonglong2*)&Wp[2 * kq + h][4 * tc];
            ulonglong2 t1 = *(const ulonglong2*)&Wp[2 * kq + h][4 * tc + 2];
            b[h][0] = t0.x; b[h][1] = t0.y; b[h][2] = t1.x; b[h][3] = t1.y;
        }
#pragma unroll
        for (int j = 0; j < 8; ++j) {
            float4 a4 = *(const float4*)&As[tr * 8 + j][4 * kq];
            u64 a01, a23;
            asm("mov.b64 %0,{%1,%2};" : "=l"(a01) : "f"(a4.x), "f"(a4.y));
            asm("mov.b64 %0,{%1,%2};" : "=l"(a23) : "f"(a4.z), "f"(a4.w));
#pragma unroll
            for (int c = 0; c < 4; ++c) {
                ffma2(acc[j][c], a01, b[0][c]);
                ffma2(acc[j][c], a23, b[1][c]);
            }
        }
    }

    // Epilogue: reduce (even,odd) halves, convert to fp16, store 8B per row.
#pragma unroll
    for (int j = 0; j < 8; ++j) {
        int gr = block_row + tr * 8 + j;
        if (gr < n) {
            float v[4];
#pragma unroll
            for (int c = 0; c < 4; ++c) {
                float lo, hi;
                asm("mov.b64 {%0,%1},%2;" : "=f"(lo), "=f"(hi) : "l"(acc[j][c]));
                v[c] = lo + hi;
            }
            __half2 h0 = __floats2half2_rn(v[0], v[1]);
            __half2 h1 = __floats2half2_rn(v[2], v[3]);
            uint2 st;
            st.x = *(unsigned*)&h0;
            st.y = *(unsigned*)&h1;
            *(uint2*)&g_tmph[gr * 32 + tc * 2] = st;
        }
    }
}

// ---------------------------------------------------------------------------
// Aggregation + bias + ELU. Warp per node; fp16 gathers (1 L2 line per edge),
// fp32 accumulate. out = ELU( dinv[i]*(sum_s dinv[s]*tmp[s]) + dinv[i]^2*tmp[i] + b )
// ---------------------------------------------------------------------------
__global__ void k_agg(const float* __restrict__ bias,
                      float* __restrict__ out, int col_off, int n) {
    int w = (blockIdx.x * blockDim.x + threadIdx.x) >> 5;
    int lane = threadIdx.x & 31;
    if (w >= n) return;
    float di = g_dinv[w];
    int beg = g_rowptr[w];
    int end = g_rowptr[w + 1];

    float ax = 0.f, ay = 0.f;
    int p = beg;
    for (; p + 3 < end; p += 4) {
        int s0 = g_col[p], s1 = g_col[p + 1], s2 = g_col[p + 2], s3 = g_col[p + 3];
        float d0 = g_dinv[s0], d1 = g_dinv[s1], d2 = g_dinv[s2], d3 = g_dinv[s3];
        float2 v0 = __half22float2(g_tmph[s0 * 32 + lane]);
        float2 v1 = __half22float2(g_tmph[s1 * 32 + lane]);
        float2 v2 = __half22float2(g_tmph[s2 * 32 + lane]);
        float2 v3 = __half22float2(g_tmph[s3 * 32 + lane]);
        ax = fmaf(d0, v0.x, ax); ay = fmaf(d0, v0.y, ay);
        ax = fmaf(d1, v1.x, ax); ay = fmaf(d1, v1.y, ay);
        ax = fmaf(d2, v2.x, ax); ay = fmaf(d2, v2.y, ay);
        ax = fmaf(d3, v3.x, ax); ay = fmaf(d3, v3.y, ay);
    }
    for (; p < end; ++p) {
        int s = g_col[p];
        float ds = g_dinv[s];
        float2 v = __half22float2(g_tmph[s * 32 + lane]);
        ax = fmaf(ds, v.x, ax);
        ay = fmaf(ds, v.y, ay);
    }
    // self-loop + symmetric norm
    float2 vs = __half22float2(g_tmph[w * 32 + lane]);
    ax = di * (ax + di * vs.x);
    ay = di * (ay + di * vs.y);
    float2 bb = ((const float2*)bias)[lane];
    ax += bb.x; ay += bb.y;
    // ELU (alpha=1)
    ax = ax > 0.f ? ax : expm1f(ax);
    ay = ay > 0.f ? ay : expm1f(ay);

    ((float2*)g_h)[w * 32 + lane] = make_float2(ax, ay);
    float* orow = out + (size_t)w * 192 + col_off;
    ((float2*)orow)[lane] = make_float2(ax, ay);
}

// ---------------------------------------------------------------------------
extern "C" void kernel_launch(void* const* d_in, const int* in_sizes, int n_in,
                              void* d_out, int out_size) {
    const float* x  = (const float*)d_in[0];
    const int*   ei = (const int*)d_in[1];
    const float* W[3] = { (const float*)d_in[2], (const float*)d_in[4], (const float*)d_in[6] };
    const float* B[3] = { (const float*)d_in[3], (const float*)d_in[5], (const float*)d_in[7] };
    int n = in_sizes[0] / 64;
    int e = in_sizes[1] / 2;
    const int* src = ei;
    const int* dst = ei + e;
    float* out = (float*)d_out;

    int nb_n = (n + 255) / 256;
    int nb_e = (e + 255) / 256;
    int nscan = (n + SCAN_B - 1) / SCAN_B;

    k_init<<<nb_n, 256>>>(n);
    k_count<<<nb_e, 256>>>(dst, e);
    k_scanA<<<nscan, SCAN_B>>>(n);
    k_scanB<<<1, SCAN_B>>>(nscan, n);
    k_scanC<<<nb_n, 256>>>(n);
    k_fill<<<nb_e, 256>>>(src, dst, e);

    int gemm_blocks = (n + 127) / 128;
    int agg_blocks = (n + 7) / 8;   // 8 warps (nodes) per 256-thread block
    for (int l = 0; l < 3; ++l) {
        k_gemm<<<gemm_blocks, 256>>>(x, l == 0 ? 1 : 0, W[l], n);
        k_agg<<<agg_blocks, 256>>>(B[l], out, l * 64, n);
    }
}

// round 4
// speedup vs baseline: 1.0955x; 1.0955x over previous
#include <cuda_runtime.h>
#include <math.h>

// Problem caps (from reference): N=50000 nodes, E=800000 edges, D=64.
#define MAXN 50000
#define MAXE 800000
#define SCAN_B 256
#define MAXBLK ((MAXN + SCAN_B - 1) / SCAN_B)   // 196

// Scratch (device globals — no allocation allowed in kernel_launch).
__device__ float g_tmp[MAXN * 64];    // h @ W
__device__ float g_h[MAXN * 64];      // layer activations (input to next layer)
__device__ float g_dinv[MAXN];        // 1/sqrt(deg+1)
__device__ int   g_deg[MAXN];
__device__ int   g_cursor[MAXN];
__device__ int   g_rowptr[MAXN + 1];
__device__ int   g_col[MAXE];         // CSR by dst: src indices
__device__ int   g_bsum[MAXBLK];      // per-block totals

// ---------------------------------------------------------------------------
// CSR build
// ---------------------------------------------------------------------------
__global__ void k_init(int n) {
    int i = blockIdx.x * blockDim.x + threadIdx.x;
    if (i < n) { g_deg[i] = 0; g_cursor[i] = 0; }
}

__global__ void k_count(const int* __restrict__ dst, int e) {
    int i = blockIdx.x * blockDim.x + threadIdx.x;
    if (i < e) atomicAdd(&g_deg[dst[i]], 1);
}

// Stage A: per-256-tile exclusive scan of g_deg -> g_rowptr (tile-local),
// tile total -> g_bsum. Also computes g_dinv (deg already in registers).
__global__ void k_scanA(int n) {
    int i = blockIdx.x * SCAN_B + threadIdx.x;
    int lane = threadIdx.x & 31, wid = threadIdx.x >> 5;
    int v = (i < n) ? g_deg[i] : 0;
    if (i < n) g_dinv[i] = rsqrtf((float)(v + 1));   // +1 self-loop

    int x = v;
#pragma unroll
    for (int o = 1; o < 32; o <<= 1) {
        int t = __shfl_up_sync(0xffffffffu, x, o);
        if (lane >= o) x += t;
    }
    __shared__ int wsum[8];
    if (lane == 31) wsum[wid] = x;
    __syncthreads();
    if (wid == 0) {
        int s = (lane < 8) ? wsum[lane] : 0;
#pragma unroll
        for (int o = 1; o < 8; o <<= 1) {
            int t = __shfl_up_sync(0xffffffffu, s, o);
            if (lane >= o) s += t;
        }
        if (lane < 8) wsum[lane] = s;
    }
    __syncthreads();
    int excl = x - v + (wid ? wsum[wid - 1] : 0);
    if (i < n) g_rowptr[i] = excl;
    if (threadIdx.x == SCAN_B - 1) g_bsum[blockIdx.x] = wsum[7];
}

// Stage C (fused with the old B): each block reduces bsum[0..b) to get its
// tile offset, adds to rowptr. Last block also writes rowptr[n] = E.
__global__ void k_scanC(int n) {
    int tid = threadIdx.x;
    int lane = tid & 31, wid = tid >> 5;
    int b = blockIdx.x;
    int s = 0;
    for (int j = tid; j < b; j += SCAN_B) s += g_bsum[j];
#pragma unroll
    for (int o = 16; o; o >>= 1) s += __shfl_down_sync(0xffffffffu, s, o);
    __shared__ int ws[8];
    __shared__ int off;
    if (lane == 0) ws[wid] = s;
    __syncthreads();
    if (tid == 0) {
        int t = 0;
#pragma unroll
        for (int j = 0; j < 8; ++j) t += ws[j];
        off = t;
    }
    __syncthreads();
    int i = b * SCAN_B + tid;
    if (i < n) g_rowptr[i] += off;
    if (b == gridDim.x - 1 && tid == 0) g_rowptr[n] = off + g_bsum[b];
}

__global__ void k_fill(const int* __restrict__ src, const int* __restrict__ dst, int e) {
    int i = blockIdx.x * blockDim.x + threadIdx.x;
    if (i < e) {
        int d = dst[i];
        int pos = g_rowptr[d] + atomicAdd(&g_cursor[d], 1);
        g_col[pos] = src[i];
    }
}

// ---------------------------------------------------------------------------
// GEMM: C[n,64] = A[n,64] @ W[64,64]   (no bias; bias folded into aggregation)
// Block: 256 threads, tile 128 rows x 64 cols, micro-tile 8x4 per thread.
// ---------------------------------------------------------------------------
__global__ void k_gemm(const float* __restrict__ Aext, int useExt,
                       const float* __restrict__ W, int n) {
    __shared__ float As[128][64];   // 32 KB
    __shared__ float Ws[64][64];    // 16 KB
    const float* A = useExt ? Aext : g_h;
    int tid = threadIdx.x;
    int block_row = blockIdx.x * 128;

    // Load W (4096 floats, float4)
    {
        const float4* w4 = (const float4*)W;
        float4* ws4 = (float4*)&Ws[0][0];
#pragma unroll
        for (int j = 0; j < 4; ++j) ws4[tid + 256 * j] = w4[tid + 256 * j];
    }
    // Load A tile (8192 floats, float4, coalesced)
    {
#pragma unroll
        for (int j = 0; j < 8; ++j) {
            int idx = tid + 256 * j;          // float4 index in tile
            int r = idx >> 4, k4 = idx & 15;  // 16 float4 per row
            int gr = block_row + r;
            float4 v = make_float4(0.f, 0.f, 0.f, 0.f);
            if (gr < n) v = ((const float4*)A)[gr * 16 + k4];
            ((float4*)&As[r][0])[k4] = v;
        }
    }
    __syncthreads();

    int tr = tid >> 4;   // 0..15 -> rows tr*8 .. tr*8+7
    int tc = tid & 15;   // 0..15 -> cols tc*4 .. tc*4+3
    float acc[8][4];
#pragma unroll
    for (int j = 0; j < 8; ++j)
#pragma unroll
        for (int c = 0; c < 4; ++c) acc[j][c] = 0.f;

#pragma unroll 4
    for (int k = 0; k < 64; ++k) {
        float4 b4 = ((const float4*)&Ws[k][0])[tc];
#pragma unroll
        for (int j = 0; j < 8; ++j) {
            float a = As[tr * 8 + j][k];
            acc[j][0] = fmaf(a, b4.x, acc[j][0]);
            acc[j][1] = fmaf(a, b4.y, acc[j][1]);
            acc[j][2] = fmaf(a, b4.z, acc[j][2]);
            acc[j][3] = fmaf(a, b4.w, acc[j][3]);
        }
    }

#pragma unroll
    for (int j = 0; j < 8; ++j) {
        int gr = block_row + tr * 8 + j;
        if (gr < n) {
            float4 v = make_float4(acc[j][0], acc[j][1], acc[j][2], acc[j][3]);
            ((float4*)&g_tmp[gr * 64])[tc] = v;
        }
    }
}

// ---------------------------------------------------------------------------
// Aggregation + bias + ELU. Warp per node, float2 per lane (64 features).
// out = ELU( dinv[i]*(sum_s dinv[s]*tmp[s]) + dinv[i]^2*tmp[i] + b )
// Unroll-by-8 edge loop for memory-level parallelism on the L2 gathers.
// ---------------------------------------------------------------------------
__global__ void k_agg(const float* __restrict__ bias,
                      float* __restrict__ out, int col_off, int n) {
    int w = (blockIdx.x * blockDim.x + threadIdx.x) >> 5;
    int lane = threadIdx.x & 31;
    if (w >= n) return;
    float di = g_dinv[w];
    int beg = g_rowptr[w];
    int end = g_rowptr[w + 1];
    const float2* t2 = (const float2*)g_tmp;

    float ax = 0.f, ay = 0.f;
    int p = beg;
    for (; p + 7 < end; p += 8) {
        int s[8]; float d[8]; float2 v[8];
#pragma unroll
        for (int j = 0; j < 8; ++j) s[j] = g_col[p + j];
#pragma unroll
        for (int j = 0; j < 8; ++j) d[j] = g_dinv[s[j]];
#pragma unroll
        for (int j = 0; j < 8; ++j) v[j] = t2[s[j] * 32 + lane];
#pragma unroll
        for (int j = 0; j < 8; ++j) {
            ax = fmaf(d[j], v[j].x, ax);
            ay = fmaf(d[j], v[j].y, ay);
        }
    }
    for (; p + 1 < end; p += 2) {
        int s0 = g_col[p], s1 = g_col[p + 1];
        float d0 = g_dinv[s0], d1 = g_dinv[s1];
        float2 v0 = t2[s0 * 32 + lane];
        float2 v1 = t2[s1 * 32 + lane];
        ax = fmaf(d0, v0.x, ax); ay = fmaf(d0, v0.y, ay);
        ax = fmaf(d1, v1.x, ax); ay = fmaf(d1, v1.y, ay);
    }
    if (p < end) {
        int s = g_col[p];
        float ds = g_dinv[s];
        float2 v = t2[s * 32 + lane];
        ax = fmaf(ds, v.x, ax);
        ay = fmaf(ds, v.y, ay);
    }
    // self-loop + symmetric norm
    float2 vs = t2[w * 32 + lane];
    ax = di * (ax + di * vs.x);
    ay = di * (ay + di * vs.y);
    float2 bb = ((const float2*)bias)[lane];
    ax += bb.x; ay += bb.y;
    // ELU (alpha=1)
    ax = ax > 0.f ? ax : expm1f(ax);
    ay = ay > 0.f ? ay : expm1f(ay);

    ((float2*)g_h)[w * 32 + lane] = make_float2(ax, ay);
    float* orow = out + (size_t)w * 192 + col_off;
    ((float2*)orow)[lane] = make_float2(ax, ay);
}

// ---------------------------------------------------------------------------
extern "C" void kernel_launch(void* const* d_in, const int* in_sizes, int n_in,
                              void* d_out, int out_size) {
    const float* x  = (const float*)d_in[0];
    const int*   ei = (const int*)d_in[1];
    const float* W[3] = { (const float*)d_in[2], (const float*)d_in[4], (const float*)d_in[6] };
    const float* B[3] = { (const float*)d_in[3], (const float*)d_in[5], (const float*)d_in[7] };
    int n = in_sizes[0] / 64;
    int e = in_sizes[1] / 2;
    const int* src = ei;
    const int* dst = ei + e;
    float* out = (float*)d_out;

    int nb_n = (n + 255) / 256;
    int nb_e = (e + 255) / 256;
    int nscan = (n + SCAN_B - 1) / SCAN_B;

    k_init<<<nb_n, 256>>>(n);
    k_count<<<nb_e, 256>>>(dst, e);
    k_scanA<<<nscan, SCAN_B>>>(n);
    k_scanC<<<nscan, SCAN_B>>>(n);
    k_fill<<<nb_e, 256>>>(src, dst, e);

    int gemm_blocks = (n + 127) / 128;
    int agg_blocks = (n + 7) / 8;   // 8 warps (nodes) per 256-thread block
    for (int l = 0; l < 3; ++l) {
        k_gemm<<<gemm_blocks, 256>>>(x, l == 0 ? 1 : 0, W[l], n);
        k_agg<<<agg_blocks, 256>>>(B[l], out, l * 64, n);
    }
}

// round 5
// speedup vs baseline: 1.1727x; 1.0705x over previous
#include <cuda_runtime.h>
#include <cuda_fp16.h>
#include <math.h>

// Problem caps (from reference): N=50000 nodes, E=800000 edges, D=64.
#define MAXN 50000
#define MAXE 800000
#define SCAN_B 256
#define MAXBLK ((MAXN + SCAN_B - 1) / SCAN_B)   // 196

// Scratch (device globals — no allocation allowed in kernel_launch).
__device__ __align__(16) __half2 g_tmph[MAXN * 32];  // dinv[r] * (h @ W)[r], fp16. 128B/row.
__device__ float g_h[MAXN * 64];      // layer activations (input to next layer)
__device__ float g_dinv[MAXN];        // 1/sqrt(deg+1)
__device__ int   g_deg[MAXN];
__device__ int   g_cursor[MAXN];      // preloaded with rowptr by scanC
__device__ int   g_rowptr[MAXN + 1];
__device__ int   g_col[MAXE];         // CSR by dst: src indices
__device__ int   g_bsum[MAXBLK];      // per-block totals

// ---------------------------------------------------------------------------
// CSR build
// ---------------------------------------------------------------------------
__global__ void k_init(int n) {
    int i = blockIdx.x * blockDim.x + threadIdx.x;
    if (i < n) g_deg[i] = 0;
}

__global__ void k_count(const int* __restrict__ dst, int e) {
    int i = blockIdx.x * blockDim.x + threadIdx.x;
    if (i < e) atomicAdd(&g_deg[dst[i]], 1);
}

// Stage A: per-256-tile exclusive scan of g_deg -> g_rowptr (tile-local),
// tile total -> g_bsum. Also computes g_dinv (deg already in registers).
__global__ void k_scanA(int n) {
    int i = blockIdx.x * SCAN_B + threadIdx.x;
    int lane = threadIdx.x & 31, wid = threadIdx.x >> 5;
    int v = (i < n) ? g_deg[i] : 0;
    if (i < n) g_dinv[i] = rsqrtf((float)(v + 1));   // +1 self-loop

    int x = v;
#pragma unroll
    for (int o = 1; o < 32; o <<= 1) {
        int t = __shfl_up_sync(0xffffffffu, x, o);
        if (lane >= o) x += t;
    }
    __shared__ int wsum[8];
    if (lane == 31) wsum[wid] = x;
    __syncthreads();
    if (wid == 0) {
        int s = (lane < 8) ? wsum[lane] : 0;
#pragma unroll
        for (int o = 1; o < 8; o <<= 1) {
            int t = __shfl_up_sync(0xffffffffu, s, o);
            if (lane >= o) s += t;
        }
        if (lane < 8) wsum[lane] = s;
    }
    __syncthreads();
    int excl = x - v + (wid ? wsum[wid - 1] : 0);
    if (i < n) g_rowptr[i] = excl;
    if (threadIdx.x == SCAN_B - 1) g_bsum[blockIdx.x] = wsum[7];
}

// Stage C: each block reduces bsum[0..b) for its tile offset, finalizes
// rowptr, and preloads g_cursor with the same value (fill's atomic base).
__global__ void k_scanC(int n) {
    int tid = threadIdx.x;
    int lane = tid & 31, wid = tid >> 5;
    int b = blockIdx.x;
    int s = 0;
    for (int j = tid; j < b; j += SCAN_B) s += g_bsum[j];
#pragma unroll
    for (int o = 16; o; o >>= 1) s += __shfl_down_sync(0xffffffffu, s, o);
    __shared__ int ws[8];
    __shared__ int off;
    if (lane == 0) ws[wid] = s;
    __syncthreads();
    if (tid == 0) {
        int t = 0;
#pragma unroll
        for (int j = 0; j < 8; ++j) t += ws[j];
        off = t;
    }
    __syncthreads();
    int i = b * SCAN_B + tid;
    if (i < n) {
        int r = g_rowptr[i] + off;
        g_rowptr[i] = r;
        g_cursor[i] = r;
    }
    if (b == gridDim.x - 1 && tid == 0) g_rowptr[n] = off + g_bsum[b];
}

__global__ void k_fill(const int* __restrict__ src, const int* __restrict__ dst, int e) {
    int i = blockIdx.x * blockDim.x + threadIdx.x;
    if (i < e) {
        int pos = atomicAdd(&g_cursor[dst[i]], 1);
        g_col[pos] = src[i];
    }
}

// ---------------------------------------------------------------------------
// GEMM: tmp'[r,64] = dinv[r] * (A[r,:] @ W), stored fp16.
// Block: 256 threads, tile 128 rows x 64 cols, micro-tile 8x4 per thread.
// fp32 math throughout; only the store quantizes.
// ---------------------------------------------------------------------------
__global__ void k_gemm(const float* __restrict__ Aext, int useExt,
                       const float* __restrict__ W, int n) {
    __shared__ float As[128][64];   // 32 KB
    __shared__ float Ws[64][64];    // 16 KB
    const float* A = useExt ? Aext : g_h;
    int tid = threadIdx.x;
    int block_row = blockIdx.x * 128;

    // Load W (4096 floats, float4)
    {
        const float4* w4 = (const float4*)W;
        float4* ws4 = (float4*)&Ws[0][0];
#pragma unroll
        for (int j = 0; j < 4; ++j) ws4[tid + 256 * j] = w4[tid + 256 * j];
    }
    // Load A tile (8192 floats, float4, coalesced)
    {
#pragma unroll
        for (int j = 0; j < 8; ++j) {
            int idx = tid + 256 * j;          // float4 index in tile
            int r = idx >> 4, k4 = idx & 15;  // 16 float4 per row
            int gr = block_row + r;
            float4 v = make_float4(0.f, 0.f, 0.f, 0.f);
            if (gr < n) v = ((const float4*)A)[gr * 16 + k4];
            ((float4*)&As[r][0])[k4] = v;
        }
    }
    __syncthreads();

    int tr = tid >> 4;   // 0..15 -> rows tr*8 .. tr*8+7
    int tc = tid & 15;   // 0..15 -> cols tc*4 .. tc*4+3
    float acc[8][4];
#pragma unroll
    for (int j = 0; j < 8; ++j)
#pragma unroll
        for (int c = 0; c < 4; ++c) acc[j][c] = 0.f;

#pragma unroll 4
    for (int k = 0; k < 64; ++k) {
        float4 b4 = ((const float4*)&Ws[k][0])[tc];
#pragma unroll
        for (int j = 0; j < 8; ++j) {
            float a = As[tr * 8 + j][k];
            acc[j][0] = fmaf(a, b4.x, acc[j][0]);
            acc[j][1] = fmaf(a, b4.y, acc[j][1]);
            acc[j][2] = fmaf(a, b4.z, acc[j][2]);
            acc[j][3] = fmaf(a, b4.w, acc[j][3]);
        }
    }

#pragma unroll
    for (int j = 0; j < 8; ++j) {
        int gr = block_row + tr * 8 + j;
        if (gr < n) {
            float ds = g_dinv[gr];
            __half2 h0 = __floats2half2_rn(ds * acc[j][0], ds * acc[j][1]);
            __half2 h1 = __floats2half2_rn(ds * acc[j][2], ds * acc[j][3]);
            uint2 st;
            st.x = *(unsigned*)&h0;
            st.y = *(unsigned*)&h1;
            *(uint2*)&g_tmph[gr * 32 + tc * 2] = st;
        }
    }
}

// ---------------------------------------------------------------------------
// Aggregation + bias + ELU. Warp per node; half2 per lane (64 features = one
// 128B line per edge gather). No per-edge dinv: it's folded into tmp'.
// out = ELU( dinv[i]*(sum_s tmp'[s] + tmp'[i]) + b )
// ---------------------------------------------------------------------------
__global__ void k_agg(const float* __restrict__ bias,
                      float* __restrict__ out, int col_off, int n) {
    int w = (blockIdx.x * blockDim.x + threadIdx.x) >> 5;
    int lane = threadIdx.x & 31;
    if (w >= n) return;
    float di = g_dinv[w];
    int beg = g_rowptr[w];
    int end = g_rowptr[w + 1];

    float ax = 0.f, ay = 0.f;
    int p = beg;
    for (; p + 7 < end; p += 8) {
        int s[8]; __half2 v[8];
#pragma unroll
        for (int j = 0; j < 8; ++j) s[j] = g_col[p + j];
#pragma unroll
        for (int j = 0; j < 8; ++j) v[j] = g_tmph[s[j] * 32 + lane];
#pragma unroll
        for (int j = 0; j < 8; ++j) {
            float2 f = __half22float2(v[j]);
            ax += f.x; ay += f.y;
        }
    }
    for (; p + 1 < end; p += 2) {
        int s0 = g_col[p], s1 = g_col[p + 1];
        float2 f0 = __half22float2(g_tmph[s0 * 32 + lane]);
        float2 f1 = __half22float2(g_tmph[s1 * 32 + lane]);
        ax += f0.x + f1.x; ay += f0.y + f1.y;
    }
    if (p < end) {
        float2 f = __half22float2(g_tmph[g_col[p] * 32 + lane]);
        ax += f.x; ay += f.y;
    }
    // self-loop (tmp' already has one dinv factor) + outer dinv + bias
    float2 vs = __half22float2(g_tmph[w * 32 + lane]);
    float2 bb = ((const float2*)bias)[lane];
    ax = fmaf(di, ax + vs.x, bb.x);
    ay = fmaf(di, ay + vs.y, bb.y);
    // ELU (alpha=1)
    ax = ax > 0.f ? ax : expm1f(ax);
    ay = ay > 0.f ? ay : expm1f(ay);

    ((float2*)g_h)[w * 32 + lane] = make_float2(ax, ay);
    float* orow = out + (size_t)w * 192 + col_off;
    ((float2*)orow)[lane] = make_float2(ax, ay);
}

// ---------------------------------------------------------------------------
extern "C" void kernel_launch(void* const* d_in, const int* in_sizes, int n_in,
                              void* d_out, int out_size) {
    const float* x  = (const float*)d_in[0];
    const int*   ei = (const int*)d_in[1];
    const float* W[3] = { (const float*)d_in[2], (const float*)d_in[4], (const float*)d_in[6] };
    const float* B[3] = { (const float*)d_in[3], (const float*)d_in[5], (const float*)d_in[7] };
    int n = in_sizes[0] / 64;
    int e = in_sizes[1] / 2;
    const int* src = ei;
    const int* dst = ei + e;
    float* out = (float*)d_out;

    int nb_n = (n + 255) / 256;
    int nb_e = (e + 255) / 256;
    int nscan = (n + SCAN_B - 1) / SCAN_B;

    k_init<<<nb_n, 256>>>(n);
    k_count<<<nb_e, 256>>>(dst, e);
    k_scanA<<<nscan, SCAN_B>>>(n);
    k_scanC<<<nscan, SCAN_B>>>(n);
    k_fill<<<nb_e, 256>>>(src, dst, e);

    int gemm_blocks = (n + 127) / 128;
    int agg_blocks = (n + 7) / 8;   // 8 warps (nodes) per 256-thread block
    for (int l = 0; l < 3; ++l) {
        k_gemm<<<gemm_blocks, 256>>>(x, l == 0 ? 1 : 0, W[l], n);
        k_agg<<<agg_blocks, 256>>>(B[l], out, l * 64, n);
    }
}

// round 6
// speedup vs baseline: 1.3586x; 1.1585x over previous
#include <cuda_runtime.h>
#include <cuda_fp16.h>
#include <math.h>

// Problem caps (from reference): N=50000 nodes, E=800000 edges, D=64.
#define MAXN 50000
#define MAXE 800000
#define SCAN_B 256
#define MAXBLK ((MAXN + SCAN_B - 1) / SCAN_B)   // 196

// Scratch (device globals — no allocation allowed in kernel_launch).
__device__ __align__(16) __half2 g_tmph[MAXN * 32];  // dinv[r] * (h @ W)[r], fp16. 128B/row.
__device__ __align__(16) __half2 g_hh[MAXN * 32];    // layer activations, fp16 (next GEMM input)
__device__ float g_dinv[MAXN];        // 1/sqrt(deg+1)
__device__ int   g_deg[MAXN];
__device__ int   g_cursor[MAXN];      // preloaded with rowptr by scanC
__device__ int   g_rowptr[MAXN + 1];
__device__ int   g_col[MAXE];         // CSR by dst: src indices
__device__ int   g_bsum[MAXBLK];      // per-block totals

// ---------------------------------------------------------------------------
// CSR build
// ---------------------------------------------------------------------------
__global__ void k_init(int n) {
    int i = blockIdx.x * blockDim.x + threadIdx.x;
    if (i < n) g_deg[i] = 0;
}

__global__ void k_count(const int* __restrict__ dst, int e) {
    int i = blockIdx.x * blockDim.x + threadIdx.x;
    if (i < e) atomicAdd(&g_deg[dst[i]], 1);
}

__global__ void k_scanA(int n) {
    int i = blockIdx.x * SCAN_B + threadIdx.x;
    int lane = threadIdx.x & 31, wid = threadIdx.x >> 5;
    int v = (i < n) ? g_deg[i] : 0;
    if (i < n) g_dinv[i] = rsqrtf((float)(v + 1));   // +1 self-loop

    int x = v;
#pragma unroll
    for (int o = 1; o < 32; o <<= 1) {
        int t = __shfl_up_sync(0xffffffffu, x, o);
        if (lane >= o) x += t;
    }
    __shared__ int wsum[8];
    if (lane == 31) wsum[wid] = x;
    __syncthreads();
    if (wid == 0) {
        int s = (lane < 8) ? wsum[lane] : 0;
#pragma unroll
        for (int o = 1; o < 8; o <<= 1) {
            int t = __shfl_up_sync(0xffffffffu, s, o);
            if (lane >= o) s += t;
        }
        if (lane < 8) wsum[lane] = s;
    }
    __syncthreads();
    int excl = x - v + (wid ? wsum[wid - 1] : 0);
    if (i < n) g_rowptr[i] = excl;
    if (threadIdx.x == SCAN_B - 1) g_bsum[blockIdx.x] = wsum[7];
}

__global__ void k_scanC(int n) {
    int tid = threadIdx.x;
    int lane = tid & 31, wid = tid >> 5;
    int b = blockIdx.x;
    int s = 0;
    for (int j = tid; j < b; j += SCAN_B) s += g_bsum[j];
#pragma unroll
    for (int o = 16; o; o >>= 1) s += __shfl_down_sync(0xffffffffu, s, o);
    __shared__ int ws[8];
    __shared__ int off;
    if (lane == 0) ws[wid] = s;
    __syncthreads();
    if (tid == 0) {
        int t = 0;
#pragma unroll
        for (int j = 0; j < 8; ++j) t += ws[j];
        off = t;
    }
    __syncthreads();
    int i = b * SCAN_B + tid;
    if (i < n) {
        int r = g_rowptr[i] + off;
        g_rowptr[i] = r;
        g_cursor[i] = r;
    }
    if (b == gridDim.x - 1 && tid == 0) g_rowptr[n] = off + g_bsum[b];
}

__global__ void k_fill(const int* __restrict__ src, const int* __restrict__ dst, int e) {
    int i = blockIdx.x * blockDim.x + threadIdx.x;
    if (i < e) {
        int pos = atomicAdd(&g_cursor[dst[i]], 1);
        g_col[pos] = src[i];
    }
}

// ---------------------------------------------------------------------------
// GEMM via HMMA mma.sync.m16n8k16: tmp'[r,:] = dinv[r] * (h[r,:] @ W), fp16 out.
// Tile 128x64, 8 warps; warp w does rows 16w..16w+15 (m16), all 64 cols
// (8 n-tiles), K=64 (4 k-steps). fp16 inputs, fp32 accumulators.
// A smem: halves [128][72] (36-word row stride -> bank (4g+t)%32, conflict-free)
// W smem: half2 pairs (k even,k odd) [32][68]    -> bank (4t+g)%32, conflict-free
// ---------------------------------------------------------------------------
#define AS_STRIDE 36   // words per A row (72 halves)
#define WP_STRIDE 68   // words per Wp row

__global__ void k_gemm(const float* __restrict__ xext, int useExt,
                       const float* __restrict__ W, int n) {
    __shared__ unsigned As[128 * AS_STRIDE];   // 18 KB
    __shared__ unsigned Wp[32 * WP_STRIDE];    // 8.5 KB
    int tid = threadIdx.x;
    int block_row = blockIdx.x * 128;

    // Pack W[64][64] fp32 -> Wp[kk][n] = half2(W[2kk][n], W[2kk+1][n])
#pragma unroll
    for (int j = 0; j < 8; ++j) {
        int idx = tid + 256 * j;            // 2048 entries
        int kk = idx >> 6, c = idx & 63;
        __half2 p = __floats2half2_rn(W[(2 * kk) * 64 + c], W[(2 * kk + 1) * 64 + c]);
        Wp[kk * WP_STRIDE + c] = *(unsigned*)&p;
    }
    // Load A tile: 128 rows x 64 halves.
    if (useExt) {
        // fp32 source: float4 -> 2 half2 (8B store)
#pragma unroll
        for (int j = 0; j < 8; ++j) {
            int idx = tid + 256 * j;        // 2048 float4
            int r = idx >> 4, c4 = idx & 15;
            int gr = block_row + r;
            float4 v = make_float4(0.f, 0.f, 0.f, 0.f);
            if (gr < n) v = ((const float4*)xext)[gr * 16 + c4];
            __half2 h0 = __floats2half2_rn(v.x, v.y);
            __half2 h1 = __floats2half2_rn(v.z, v.w);
            uint2 st; st.x = *(unsigned*)&h0; st.y = *(unsigned*)&h1;
            *(uint2*)&As[r * AS_STRIDE + c4 * 2] = st;
        }
    } else {
        // fp16 source (g_hh): uint2 = 4 halves
#pragma unroll
        for (int j = 0; j < 8; ++j) {
            int idx = tid + 256 * j;
            int r = idx >> 4, c4 = idx & 15;
            int gr = block_row + r;
            uint2 v = make_uint2(0u, 0u);
            if (gr < n) v = ((const uint2*)g_hh)[gr * 16 + c4];
            *(uint2*)&As[r * AS_STRIDE + c4 * 2] = v;
        }
    }
    __syncthreads();

    int w = tid >> 5, l = tid & 31;
    int t = l & 3, g = l >> 2;
    int r0 = w * 16 + g;                 // rows r0, r0+8

    float acc[8][4];
#pragma unroll
    for (int nt = 0; nt < 8; ++nt)
#pragma unroll
        for (int c = 0; c < 4; ++c) acc[nt][c] = 0.f;

#pragma unroll
    for (int ks = 0; ks < 4; ++ks) {
        unsigned a0 = As[r0 * AS_STRIDE + 8 * ks + t];
        unsigned a1 = As[(r0 + 8) * AS_STRIDE + 8 * ks + t];
        unsigned a2 = As[r0 * AS_STRIDE + 8 * ks + t + 4];
        unsigned a3 = As[(r0 + 8) * AS_STRIDE + 8 * ks + t + 4];
#pragma unroll
        for (int nt = 0; nt < 8; ++nt) {
            unsigned b0 = Wp[(8 * ks + t) * WP_STRIDE + 8 * nt + g];
            unsigned b1 = Wp[(8 * ks + t + 4) * WP_STRIDE + 8 * nt + g];
            asm("mma.sync.aligned.m16n8k16.row.col.f32.f16.f16.f32 "
                "{%0,%1,%2,%3},{%4,%5,%6,%7},{%8,%9},{%0,%1,%2,%3};"
                : "+f"(acc[nt][0]), "+f"(acc[nt][1]), "+f"(acc[nt][2]), "+f"(acc[nt][3])
                : "r"(a0), "r"(a1), "r"(a2), "r"(a3), "r"(b0), "r"(b1));
        }
    }

    // Epilogue: scale by dinv, store fp16. c0,c1 -> row r0 cols (2t,2t+1)+8nt;
    // c2,c3 -> row r0+8.
    int gr0 = block_row + r0;
    int gr1 = gr0 + 8;
    float ds0 = (gr0 < n) ? g_dinv[gr0] : 0.f;
    float ds1 = (gr1 < n) ? g_dinv[gr1] : 0.f;
#pragma unroll
    for (int nt = 0; nt < 8; ++nt) {
        if (gr0 < n) {
            __half2 h = __floats2half2_rn(ds0 * acc[nt][0], ds0 * acc[nt][1]);
            g_tmph[gr0 * 32 + 4 * nt + t] = h;
        }
        if (gr1 < n) {
            __half2 h = __floats2half2_rn(ds1 * acc[nt][2], ds1 * acc[nt][3]);
            g_tmph[gr1 * 32 + 4 * nt + t] = h;
        }
    }
}

// ---------------------------------------------------------------------------
// Aggregation + bias + ELU. Warp per node; half2 per lane (64 features = one
// 128B line per edge gather). out = ELU( dinv[i]*(sum_s tmp'[s] + tmp'[i]) + b )
// Writes g_hh (fp16, next GEMM input) and d_out slice (fp32, pitch 192).
// ---------------------------------------------------------------------------
__global__ void k_agg(const float* __restrict__ bias,
                      float* __restrict__ out, int col_off, int n) {
    int w = (blockIdx.x * blockDim.x + threadIdx.x) >> 5;
    int lane = threadIdx.x & 31;
    if (w >= n) return;
    float di = g_dinv[w];
    int beg = g_rowptr[w];
    int end = g_rowptr[w + 1];

    float ax = 0.f, ay = 0.f;
    int p = beg;
    for (; p + 7 < end; p += 8) {
        int s[8]; __half2 v[8];
#pragma unroll
        for (int j = 0; j < 8; ++j) s[j] = g_col[p + j];
#pragma unroll
        for (int j = 0; j < 8; ++j) v[j] = g_tmph[s[j] * 32 + lane];
#pragma unroll
        for (int j = 0; j < 8; ++j) {
            float2 f = __half22float2(v[j]);
            ax += f.x; ay += f.y;
        }
    }
    for (; p + 1 < end; p += 2) {
        int s0 = g_col[p], s1 = g_col[p + 1];
        float2 f0 = __half22float2(g_tmph[s0 * 32 + lane]);
        float2 f1 = __half22float2(g_tmph[s1 * 32 + lane]);
        ax += f0.x + f1.x; ay += f0.y + f1.y;
    }
    if (p < end) {
        float2 f = __half22float2(g_tmph[g_col[p] * 32 + lane]);
        ax += f.x; ay += f.y;
    }
    // self-loop (tmp' already has one dinv factor) + outer dinv + bias
    float2 vs = __half22float2(g_tmph[w * 32 + lane]);
    float2 bb = ((const float2*)bias)[lane];
    ax = fmaf(di, ax + vs.x, bb.x);
    ay = fmaf(di, ay + vs.y, bb.y);
    // ELU (alpha=1)
    ax = ax > 0.f ? ax : expm1f(ax);
    ay = ay > 0.f ? ay : expm1f(ay);

    g_hh[w * 32 + lane] = __floats2half2_rn(ax, ay);
    float* orow = out + (size_t)w * 192 + col_off;
    ((float2*)orow)[lane] = make_float2(ax, ay);
}

// ---------------------------------------------------------------------------
extern "C" void kernel_launch(void* const* d_in, const int* in_sizes, int n_in,
                              void* d_out, int out_size) {
    const float* x  = (const float*)d_in[0];
    const int*   ei = (const int*)d_in[1];
    const float* W[3] = { (const float*)d_in[2], (const float*)d_in[4], (const float*)d_in[6] };
    const float* B[3] = { (const float*)d_in[3], (const float*)d_in[5], (const float*)d_in[7] };
    int n = in_sizes[0] / 64;
    int e = in_sizes[1] / 2;
    const int* src = ei;
    const int* dst = ei + e;
    float* out = (float*)d_out;

    int nb_n = (n + 255) / 256;
    int nb_e = (e + 255) / 256;
    int nscan = (n + SCAN_B - 1) / SCAN_B;

    k_init<<<nb_n, 256>>>(n);
    k_count<<<nb_e, 256>>>(dst, e);
    k_scanA<<<nscan, SCAN_B>>>(n);
    k_scanC<<<nscan, SCAN_B>>>(n);
    k_fill<<<nb_e, 256>>>(src, dst, e);

    int gemm_blocks = (n + 127) / 128;
    int agg_blocks = (n + 7) / 8;   // 8 warps (nodes) per 256-thread block
    for (int l = 0; l < 3; ++l) {
        k_gemm<<<gemm_blocks, 256>>>(x, l == 0 ? 1 : 0, W[l], n);
        k_agg<<<agg_blocks, 256>>>(B[l], out, l * 64, n);
    }
}